// round 5
// baseline (speedup 1.0000x reference)
#include <cuda_runtime.h>
#include <cstddef>
#include <cstdint>

// Problem constants:
//   C_IN=8, H=W=32, C_OUT=32, K=4, S=2, P=1, HO=WO=16
//   IN_FEAT = 8192, OUT_FEAT = 8192
// Output layout (flattened tuple):
//   [0, 16384)                    : out_bounds [2, 32, 16, 16]
//   [16384, 16384 + 8192*8192)    : W_mat [8192, 8192]
//   [16384 + 8192*8192, +8192)    : bias_backsub [8192]

#define C_IN     8
#define C_OUT    32
#define IN_FEAT  8192
#define OUT_FEAT 8192
#define WMAT_OFF 16384ULL
#define BB_OFF   (16384ULL + 8192ULL * 8192ULL)

#define BOUNDS_BLOCKS 32
#define FILL_BLOCKS   2368       // 148 SMs * 16
#define BLOCK_THREADS 256
#define WARPS_PER_BLOCK (BLOCK_THREADS / 32)

// W_mat in 4KB "chunks": one chunk = one (row o, input channel ci)
// = 32h x 32w floats = 256 float4. Total = 8192 rows * 8 ci = 65536 chunks.
#define TOTAL_CHUNKS 65536u

// L2 is ~126 MB. Pin a 96 MB prefix of W_mat in L2 via evict_last policy:
// under graph-replay steady state those lines are rewritten in-place in L2
// and don't generate DRAM traffic. 96 MB / 4 KB = 24576 chunks.
#define RESIDENT_CHUNKS 24576u

__device__ __forceinline__ uint64_t make_policy_evict_last() {
    uint64_t pol;
    asm("createpolicy.fractional.L2::evict_last.b64 %0, 1.0;" : "=l"(pol));
    return pol;
}
__device__ __forceinline__ uint64_t make_policy_evict_first() {
    uint64_t pol;
    asm("createpolicy.fractional.L2::evict_first.b64 %0, 1.0;" : "=l"(pol));
    return pol;
}
__device__ __forceinline__ void st_hint(float4* p, float4 v, uint64_t pol) {
    asm volatile("st.global.L2::cache_hint.v4.f32 [%0], {%1,%2,%3,%4}, %5;"
                 :: "l"(p), "f"(v.x), "f"(v.y), "f"(v.z), "f"(v.w), "l"(pol)
                 : "memory");
}

__global__ void __launch_bounds__(BLOCK_THREADS)
fused_deeppoly_kernel(const float* __restrict__ bounds,   // [2, 8192] (l, u)
                      const float* __restrict__ weight,   // [32, 8, 4, 4]
                      const float* __restrict__ bias,     // [32]
                      float* __restrict__ out) {
    unsigned bid = blockIdx.x;
    unsigned tid = threadIdx.x;

    if (bid < BOUNDS_BLOCKS) {
        // ------------------------------------------------------------------
        // Interval conv bounds. Equals both forward-propagated and
        // back-substituted bounds -> reference's tighten is a no-op
        // (verified R1-R3, rel_err 2e-7).
        // ------------------------------------------------------------------
        unsigned o = bid * BLOCK_THREADS + tid;      // < 8192
        unsigned co = o >> 8;
        unsigned ho = (o >> 4) & 15u;
        unsigned wo = o & 15u;

        const float* __restrict__ l = bounds;
        const float* __restrict__ u = bounds + IN_FEAT;

        float b = __ldg(&bias[co]);
        float lo = b;
        float up = b;

        #pragma unroll
        for (int ci = 0; ci < C_IN; ci++) {
            #pragma unroll
            for (int kh = 0; kh < 4; kh++) {
                int h = 2 * (int)ho - 1 + kh;
                if ((unsigned)h >= 32u) continue;
                #pragma unroll
                for (int kw = 0; kw < 4; kw++) {
                    int w = 2 * (int)wo - 1 + kw;
                    if ((unsigned)w >= 32u) continue;
                    float wv = __ldg(&weight[co * 128u + (unsigned)ci * 16u +
                                             (unsigned)kh * 4u + (unsigned)kw]);
                    float wp = fmaxf(wv, 0.0f);
                    float wm = fminf(wv, 0.0f);
                    unsigned in = (unsigned)ci * 1024u +
                                  (unsigned)h * 32u + (unsigned)w;
                    float lv = __ldg(&l[in]);
                    float uv = __ldg(&u[in]);
                    lo = fmaf(wp, lv, fmaf(wm, uv, lo));
                    up = fmaf(wp, uv, fmaf(wm, lv, up));
                }
            }
        }

        out[o] = lo;                 // out_bounds[0]
        out[OUT_FEAT + o] = up;      // out_bounds[1]
        out[BB_OFF + o] = b;         // bias_backsub
        return;
    }

    // ----------------------------------------------------------------------
    // Fill+scatter: one warp per 4KB chunk (grid-stride). Chunk body = 8
    // warp-wide STG.128 iterations (512B each); "strip intersects window"
    // test is warp-uniform so 6-7 of 8 iterations are pure zero stores.
    // First RESIDENT_CHUNKS chunks stored with evict_last policy (L2-pinned);
    // the rest with evict_first (streamed to DRAM, protects the pinned set).
    // ----------------------------------------------------------------------
    float4* __restrict__ wmat4 = (float4*)(out + WMAT_OFF);

    const uint64_t pol_last  = make_policy_evict_last();
    const uint64_t pol_first = make_policy_evict_first();

    unsigned lane = tid & 31u;
    unsigned warp = (bid - BOUNDS_BLOCKS) * WARPS_PER_BLOCK + (tid >> 5);
    const unsigned nwarps = FILL_BLOCKS * WARPS_PER_BLOCK;

    for (unsigned chunk = warp; chunk < TOTAL_CHUNKS; chunk += nwarps) {
        unsigned o  = chunk >> 3;
        unsigned ci = chunk & 7u;
        unsigned co = o >> 8;
        unsigned ho = (o >> 4) & 15u;
        unsigned wo = o & 15u;

        float4* __restrict__ base = wmat4 + (size_t)chunk * 256u;
        const float* __restrict__ wrow = weight + co * 128u + ci * 16u;

        int hwin0 = 2 * (int)ho - 1;                     // window h start
        int kw0 = (int)((lane & 7u) << 2) - 2 * (int)wo + 1;
        int hl = (int)(lane >> 3);                       // 0..3
        uint64_t pol = (chunk < RESIDENT_CHUNKS) ? pol_last : pol_first;

        #pragma unroll
        for (int it = 0; it < 8; it++) {
            float4 v = make_float4(0.f, 0.f, 0.f, 0.f);
            // Warp-uniform: strip [4it, 4it+4) vs window [hwin0, hwin0+4)
            if (4 * it + 3 >= hwin0 && 4 * it <= hwin0 + 3) {
                int kh = 4 * it + hl - hwin0;
                if ((unsigned)kh < 4u && kw0 > -4 && kw0 < 4) {
                    const float* __restrict__ wp = wrow + (unsigned)kh * 4u;
                    if ((unsigned)(kw0 + 0) < 4u) v.x = __ldg(&wp[kw0 + 0]);
                    if ((unsigned)(kw0 + 1) < 4u) v.y = __ldg(&wp[kw0 + 1]);
                    if ((unsigned)(kw0 + 2) < 4u) v.z = __ldg(&wp[kw0 + 2]);
                    if ((unsigned)(kw0 + 3) < 4u) v.w = __ldg(&wp[kw0 + 3]);
                }
            }
            st_hint(&base[it * 32 + lane], v, pol);
        }
    }
}

extern "C" void kernel_launch(void* const* d_in, const int* in_sizes, int n_in,
                              void* d_out, int out_size) {
    const float* bounds = (const float*)d_in[0];  // [2, 8, 32, 32]
    const float* weight = (const float*)d_in[1];  // [32, 8, 4, 4]
    const float* bias   = (const float*)d_in[2];  // [32]
    // d_in[3] = assignment (unused by reference forward)

    float* out = (float*)d_out;

    fused_deeppoly_kernel<<<BOUNDS_BLOCKS + FILL_BLOCKS, BLOCK_THREADS>>>(
        bounds, weight, bias, out);
}